// round 11
// baseline (speedup 1.0000x reference)
#include <cuda_runtime.h>
#include <cuda_bf16.h>
#include <cstdint>

#define N_NODES 100000
#define DIM 128
#define NNZ 1600000
#define NBLK ((N_NODES + 255) / 256)    // 391 scan blocks
#define M_TILE 64
#define N_TILES ((N_NODES + M_TILE - 1) / M_TILE)   // 1563
#define GEMM_GRID 152                   // persistent blocks (GB300: 152 SMs)

// -------- device-global scratch (no allocations allowed) --------
__device__ float g_xa[(size_t)N_NODES * DIM];            // x ping buffer
__device__ float g_xb[(size_t)N_NODES * DIM];            // x pong buffer
__device__ __nv_bfloat16 g_wbh[2 * 256 * 128];           // pre-split weights hi, k-major [layer][k][n]
__device__ __nv_bfloat16 g_wbl[2 * 256 * 128];           // pre-split weights lo
__device__ float g_bias[2 * 128];                         // combined bias per layer
__device__ int   g_cnt[N_NODES];                          // CSR histogram (zeroed by pscan after use)
__device__ int   g_bsum[NBLK];                            // per-block sums
__device__ int   g_boff[NBLK];                            // per-block exclusive offsets
__device__ int   g_ptr[N_NODES + 1];                      // CSR row pointers
__device__ int   g_wptr[N_NODES];                         // scatter cursors
__device__ int2  g_edge[NNZ];                             // packed (col, val) sorted by row

__device__ __forceinline__ void bf16_split(float v, __nv_bfloat16& h, __nv_bfloat16& l) {
    h = __float2bfloat16(v);
    l = __float2bfloat16(v - __bfloat162float(h));
}

// ================= fused setup: init-x/out + weight prep + histogram =================
#define INIT_N (N_NODES * 32)           // 3,200,000 float4 copies
#define WP_N   (2 * 256 * 128)          // 65,536 weight elements
#define SETUP_N (INIT_N + WP_N + NNZ)

__global__ void __launch_bounds__(256) setup_kernel(const float* __restrict__ emb,
                                                    float* __restrict__ out,
                                                    const float* __restrict__ W1,
                                                    const float* __restrict__ b1,
                                                    const float* __restrict__ W2,
                                                    const float* __restrict__ b2,
                                                    const int* __restrict__ rows) {
    int t = blockIdx.x * blockDim.x + threadIdx.x;
    if (t < INIT_N) {                                  // ---- init ----
        int row = t >> 5, c = t & 31;
        float4 e = ((const float4*)emb)[t];
        ((float4*)g_xa)[t] = e;
        ((float4*)out)[row * 96 + c] = e;
    } else if (t < INIT_N + WP_N) {                    // ---- weight prep ----
        int idx = t - INIT_N;
        int n = idx & 127;
        int k = (idx >> 7) & 255;
        int layer = idx >> 15;
        float w = (k < 128) ? W1[layer * 16384 + n * 128 + k]
                            : W2[layer * 16384 + n * 128 + (k - 128)];
        __nv_bfloat16 h, l;
        bf16_split(w, h, l);
        g_wbh[idx] = h;
        g_wbl[idx] = l;
        if (idx < 256) {
            int L = idx >> 7, nn = idx & 127;
            g_bias[idx] = b1[L * 128 + nn] + b2[L * 128 + nn];
        }
    } else if (t < SETUP_N) {                          // ---- histogram ----
        int e = t - (INIT_N + WP_N);
        atomicAdd(&g_cnt[rows[e]], 1);
    }
}

// ================= CSR scan (3 phases) =================
__global__ void __launch_bounds__(256) bsum_kernel() {
    int g = blockIdx.x * 256 + threadIdx.x;
    int v = (g < N_NODES) ? g_cnt[g] : 0;
#pragma unroll
    for (int d = 16; d > 0; d >>= 1) v += __shfl_xor_sync(0xffffffffu, v, d);
    __shared__ int ws[8];
    if ((threadIdx.x & 31) == 0) ws[threadIdx.x >> 5] = v;
    __syncthreads();
    if (threadIdx.x == 0) {
        int s = 0;
#pragma unroll
        for (int i = 0; i < 8; i++) s += ws[i];
        g_bsum[blockIdx.x] = s;
    }
}

__global__ void __launch_bounds__(512) bscan_kernel() {
    int t = threadIdx.x;
    int lane = t & 31, warp = t >> 5;
    int v = (t < NBLK) ? g_bsum[t] : 0;
    int s = v;
#pragma unroll
    for (int d = 1; d < 32; d <<= 1) {
        int u = __shfl_up_sync(0xffffffffu, s, d);
        if (lane >= d) s += u;
    }
    __shared__ int ws[16];
    if (lane == 31) ws[warp] = s;
    __syncthreads();
    if (warp == 0) {                          // all 32 lanes shuffle
        int w = (lane < 16) ? ws[lane] : 0;
#pragma unroll
        for (int d = 1; d < 32; d <<= 1) {
            int u = __shfl_up_sync(0xffffffffu, w, d);
            if (lane >= d) w += u;
        }
        if (lane < 16) ws[lane] = w;
    }
    __syncthreads();
    int excl = s - v + (warp > 0 ? ws[warp - 1] : 0);
    if (t < NBLK) g_boff[t] = excl;
}

__global__ void __launch_bounds__(256) pscan_kernel() {
    int t = threadIdx.x;
    int lane = t & 31, warp = t >> 5;
    int g = blockIdx.x * 256 + t;
    int v = (g < N_NODES) ? g_cnt[g] : 0;
    int s = v;
#pragma unroll
    for (int d = 1; d < 32; d <<= 1) {
        int u = __shfl_up_sync(0xffffffffu, s, d);
        if (lane >= d) s += u;
    }
    __shared__ int ws[8];
    if (lane == 31) ws[warp] = s;
    __syncthreads();
    if (warp == 0) {                          // all 32 lanes shuffle
        int w = (lane < 8) ? ws[lane] : 0;
#pragma unroll
        for (int d = 1; d < 32; d <<= 1) {
            int u = __shfl_up_sync(0xffffffffu, w, d);
            if (lane >= d) w += u;
        }
        if (lane < 8) ws[lane] = w;
    }
    __syncthreads();
    int excl = s - v + (warp > 0 ? ws[warp - 1] : 0) + g_boff[blockIdx.x];
    if (g < N_NODES) {
        g_ptr[g]  = excl;
        g_wptr[g] = excl;
        g_cnt[g]  = 0;                        // reset for next graph replay
        if (g == N_NODES - 1) g_ptr[N_NODES] = NNZ;
    }
}

__global__ void __launch_bounds__(256) scatter_kernel(const int* __restrict__ rows,
                                                      const int* __restrict__ cols,
                                                      const float* __restrict__ vals) {
    int e = blockIdx.x * blockDim.x + threadIdx.x;
    if (e >= NNZ) return;
    int pos = atomicAdd(&g_wptr[rows[e]], 1);
    g_edge[pos] = make_int2(cols[e], __float_as_int(vals[e]));
}

// ==================== mma.sync / cp.async helpers (baseline ISA) ====================
__device__ __forceinline__ uint32_t smem_u32(const void* p) {
    uint32_t a;
    asm("{ .reg .u64 t; cvta.to.shared.u64 t, %1; cvt.u32.u64 %0, t; }" : "=r"(a) : "l"(p));
    return a;
}
__device__ __forceinline__ void ldsm_x4(uint32_t* r, uint32_t addr) {
    asm volatile("ldmatrix.sync.aligned.m8n8.x4.shared.b16 {%0,%1,%2,%3}, [%4];"
                 : "=r"(r[0]), "=r"(r[1]), "=r"(r[2]), "=r"(r[3]) : "r"(addr));
}
__device__ __forceinline__ void ldsm_x4_t(uint32_t* r, uint32_t addr) {
    asm volatile("ldmatrix.sync.aligned.m8n8.x4.trans.shared.b16 {%0,%1,%2,%3}, [%4];"
                 : "=r"(r[0]), "=r"(r[1]), "=r"(r[2]), "=r"(r[3]) : "r"(addr));
}
__device__ __forceinline__ void mma_bf16(float* d, const uint32_t* a, const uint32_t* b) {
    asm volatile("mma.sync.aligned.m16n8k16.row.col.f32.bf16.bf16.f32 "
                 "{%0,%1,%2,%3}, {%4,%5,%6,%7}, {%8,%9}, {%0,%1,%2,%3};"
                 : "+f"(d[0]), "+f"(d[1]), "+f"(d[2]), "+f"(d[3])
                 : "r"(a[0]), "r"(a[1]), "r"(a[2]), "r"(a[3]), "r"(b[0]), "r"(b[1]));
}
__device__ __forceinline__ void cp16(uint32_t dst, const void* src, bool pred) {
    asm volatile("cp.async.cg.shared.global [%0], [%1], 16, %2;"
                 :: "r"(dst), "l"(src), "r"(pred ? 16u : 0u));
}
__device__ __forceinline__ void cp_commit() {
    asm volatile("cp.async.commit_group;" ::: "memory");
}

// ================= FUSED persistent gather + bf16-split MMA layer =================
// Reads x_src (frozen this layer), writes x_dst + out — ping-pong kills the
// cross-block read/write race on x. Per 64-row tile: warp-per-row gather ->
// bf16 hi/lo split straight into SMEM A -> MMA (K=256) -> fused epilogue.
// SMEM: BH[256x272] | BL[256x272] | AH[64x528] | AL[64x528]; C aliases AH.
#define RSTRIDE_B 272
#define ASTR 528                                // 512B (K=256 bf16) + 16B pad
#define OFF_BH 0
#define OFF_BL (256 * RSTRIDE_B)                // 69632
#define OFF_AH (2 * 256 * RSTRIDE_B)            // 139264
#define OFF_AL (OFF_AH + M_TILE * ASTR)         // 173056
#define OFF_C  OFF_AH                           // 64*132*4 = 33792 == AH size
#define GEMM_SMEM (OFF_AL + M_TILE * ASTR)      // 206848

__global__ void __launch_bounds__(256, 1) fused_layer_kernel(const float* __restrict__ x_src,
                                                             float* __restrict__ x_dst,
                                                             float* __restrict__ out,
                                                             int layer) {
    extern __shared__ char smem[];
    uint32_t sbase = smem_u32(smem);
    int tid = threadIdx.x;
    int wid = tid >> 5, lid = tid & 31;
    int warp_m = wid >> 2, warp_n = wid & 3;      // 2x4 warp grid: 32-row x 32-col warp tiles
    float4 bias4 = ((const float4*)(g_bias + layer * 128))[lid];
    const float4* gx4 = (const float4*)x_src;

    // ---- stage B ONCE (cp.async; resident for all tiles) ----
    {
        const char* gwh = (const char*)g_wbh + (size_t)layer * 65536;
        const char* gwl = (const char*)g_wbl + (size_t)layer * 65536;
        for (int i = tid; i < 8192; i += 256) {
            int m = i >> 12, rem = i & 4095, r = rem >> 4, q = rem & 15;
            uint32_t dst = sbase + (m ? OFF_BL : OFF_BH) + r * RSTRIDE_B + q * 16;
            const char* src = (m ? gwl : gwh) + r * 256 + q * 16;
            cp16(dst, src, true);
        }
        cp_commit();
        asm volatile("cp.async.wait_group 0;" ::: "memory");
    }
    __syncthreads();

    // ---- persistent tile loop ----
    for (int tile = blockIdx.x; tile < N_TILES; tile += gridDim.x) {
        int row0 = tile * M_TILE;

        // ===== gather phase: warp per row, 8 rows per pass, 8 passes =====
#pragma unroll 1
        for (int it = 0; it < 8; it++) {
            int r = it * 8 + wid;
            int gr = row0 + r;
            if (gr < N_NODES) {
                char* ah = smem + OFF_AH + r * ASTR;
                char* al = smem + OFF_AL + r * ASTR;
                int n0 = g_ptr[gr], n1 = g_ptr[gr + 1];
                float4 acc = make_float4(0.f, 0.f, 0.f, 0.f);
                int e = n0;
                for (; e + 4 <= n1; e += 4) {
                    int2 e0 = __ldg(&g_edge[e]),     e1 = __ldg(&g_edge[e + 1]);
                    int2 e2 = __ldg(&g_edge[e + 2]), e3 = __ldg(&g_edge[e + 3]);
                    float4 x0 = gx4[(size_t)e0.x * 32 + lid];
                    float4 x1 = gx4[(size_t)e1.x * 32 + lid];
                    float4 x2 = gx4[(size_t)e2.x * 32 + lid];
                    float4 x3 = gx4[(size_t)e3.x * 32 + lid];
                    float v0 = __int_as_float(e0.y), v1 = __int_as_float(e1.y);
                    float v2 = __int_as_float(e2.y), v3 = __int_as_float(e3.y);
                    acc.x = fmaf(v0, x0.x, acc.x); acc.y = fmaf(v0, x0.y, acc.y);
                    acc.z = fmaf(v0, x0.z, acc.z); acc.w = fmaf(v0, x0.w, acc.w);
                    acc.x = fmaf(v1, x1.x, acc.x); acc.y = fmaf(v1, x1.y, acc.y);
                    acc.z = fmaf(v1, x1.z, acc.z); acc.w = fmaf(v1, x1.w, acc.w);
                    acc.x = fmaf(v2, x2.x, acc.x); acc.y = fmaf(v2, x2.y, acc.y);
                    acc.z = fmaf(v2, x2.z, acc.z); acc.w = fmaf(v2, x2.w, acc.w);
                    acc.x = fmaf(v3, x3.x, acc.x); acc.y = fmaf(v3, x3.y, acc.y);
                    acc.z = fmaf(v3, x3.z, acc.z); acc.w = fmaf(v3, x3.w, acc.w);
                }
                for (; e < n1; e++) {
                    int2 ed = __ldg(&g_edge[e]);
                    float v = __int_as_float(ed.y);
                    float4 xc = gx4[(size_t)ed.x * 32 + lid];
                    acc.x = fmaf(v, xc.x, acc.x);
                    acc.y = fmaf(v, xc.y, acc.y);
                    acc.z = fmaf(v, xc.z, acc.z);
                    acc.w = fmaf(v, xc.w, acc.w);
                }
                float4 xr = gx4[(size_t)gr * 32 + lid];
                float a[4] = {acc.x + xr.x, acc.y + xr.y, acc.z + xr.z, acc.w + xr.w};
                float b[4] = {acc.x * xr.x, acc.y * xr.y, acc.z * xr.z, acc.w * xr.w};
                __nv_bfloat16 ha[4], la[4], hb[4], lb[4];
#pragma unroll
                for (int j = 0; j < 4; j++) { bf16_split(a[j], ha[j], la[j]); bf16_split(b[j], hb[j], lb[j]); }
                // k = lid*4 .. lid*4+3 : side+x at bytes [lid*8), side*x at [256 + lid*8)
                *(uint2*)(ah + lid * 8)       = *(uint2*)ha;
                *(uint2*)(ah + 256 + lid * 8) = *(uint2*)hb;
                *(uint2*)(al + lid * 8)       = *(uint2*)la;
                *(uint2*)(al + 256 + lid * 8) = *(uint2*)lb;
            }
            // rows with gr >= N_NODES keep stale smem; their D rows are never
            // stored (per-row independence makes them harmless).
        }
        __syncthreads();

        // ===== MMA phase: K = 256 in 16 k16 steps =====
        float acc[2][4][4];
#pragma unroll
        for (int mf = 0; mf < 2; mf++)
#pragma unroll
            for (int nf = 0; nf < 4; nf++)
#pragma unroll
                for (int q = 0; q < 4; q++) acc[mf][nf][q] = 0.f;

#pragma unroll
        for (int k16 = 0; k16 < 16; k16++) {
            int k0 = k16 * 16;
            uint32_t ah[2][4], al[2][4];
            int ar = (lid & 15);
            int ac = k0 * 2 + ((lid >> 4) << 4);   // byte col: (k0 + (lid>>4)*8)*2
#pragma unroll
            for (int mf = 0; mf < 2; mf++) {
                int r = warp_m * 32 + mf * 16 + ar;
                ldsm_x4(ah[mf], sbase + OFF_AH + r * ASTR + ac);
                ldsm_x4(al[mf], sbase + OFF_AL + r * ASTR + ac);
            }
            uint32_t bh[4][2], bl[4][2];
            int br = k0 + (lid & 15);
#pragma unroll
            for (int np = 0; np < 2; np++) {
                int nc = (warp_n * 32 + np * 16 + ((lid >> 4) << 3)) * 2;
                uint32_t t[4];
                ldsm_x4_t(t, sbase + OFF_BH + br * RSTRIDE_B + nc);
                bh[np * 2][0] = t[0]; bh[np * 2][1] = t[1];
                bh[np * 2 + 1][0] = t[2]; bh[np * 2 + 1][1] = t[3];
                ldsm_x4_t(t, sbase + OFF_BL + br * RSTRIDE_B + nc);
                bl[np * 2][0] = t[0]; bl[np * 2][1] = t[1];
                bl[np * 2 + 1][0] = t[2]; bl[np * 2 + 1][1] = t[3];
            }
#pragma unroll
            for (int mf = 0; mf < 2; mf++)
#pragma unroll
                for (int nf = 0; nf < 4; nf++) {
                    mma_bf16(acc[mf][nf], ah[mf], bh[nf]);  // hi*hi
                    mma_bf16(acc[mf][nf], ah[mf], bl[nf]);  // hi*lo
                    mma_bf16(acc[mf][nf], al[mf], bh[nf]);  // lo*hi
                }
        }
        __syncthreads();   // all ldmatrix reads done -> safe to alias C over AH

        // ---- dump accumulators to SMEM C tile ----
        float* Cs = (float*)(smem + OFF_C);
#pragma unroll
        for (int mf = 0; mf < 2; mf++)
#pragma unroll
            for (int nf = 0; nf < 4; nf++) {
                int r = warp_m * 32 + mf * 16 + (lid >> 2);
                int cc = warp_n * 32 + nf * 8 + (lid & 3) * 2;
                *(float2*)&Cs[r * 132 + cc]       = make_float2(acc[mf][nf][0], acc[mf][nf][1]);
                *(float2*)&Cs[(r + 8) * 132 + cc] = make_float2(acc[mf][nf][2], acc[mf][nf][3]);
            }
        __syncthreads();

        // ---- epilogue: warp per row — bias + leaky + L2 norm + dual store ----
#pragma unroll
        for (int it = 0; it < 8; it++) {
            int row = it * 8 + wid;
            int gr = row0 + row;
            float4 v = *(float4*)&Cs[row * 132 + lid * 4];
            float t0 = v.x + bias4.x, t1 = v.y + bias4.y;
            float t2 = v.z + bias4.z, t3 = v.w + bias4.w;
            t0 = (t0 > 0.f) ? t0 : 0.01f * t0;
            t1 = (t1 > 0.f) ? t1 : 0.01f * t1;
            t2 = (t2 > 0.f) ? t2 : 0.01f * t2;
            t3 = (t3 > 0.f) ? t3 : 0.01f * t3;
            float ss = fmaf(t0, t0, fmaf(t1, t1, fmaf(t2, t2, t3 * t3)));
            ss += __shfl_xor_sync(0xffffffffu, ss, 16);
            ss += __shfl_xor_sync(0xffffffffu, ss, 8);
            ss += __shfl_xor_sync(0xffffffffu, ss, 4);
            ss += __shfl_xor_sync(0xffffffffu, ss, 2);
            ss += __shfl_xor_sync(0xffffffffu, ss, 1);
            float sc = 1.0f / fmaxf(sqrtf(ss), 1e-12f);
            if (gr < N_NODES) {
                float4 o = make_float4(t0 * sc, t1 * sc, t2 * sc, t3 * sc);
                ((float4*)&x_dst[(size_t)gr * 128])[lid] = o;
                ((float4*)&out[(size_t)gr * 384 + (size_t)(layer + 1) * 128])[lid] = o;
            }
        }
        __syncthreads();   // epilogue Cs reads done -> next tile may overwrite A
    }
}

// ================= launch =================
extern "C" void kernel_launch(void* const* d_in, const int* in_sizes, int n_in,
                              void* d_out, int out_size) {
    const int*   adj_row  = (const int*)d_in[0];
    const int*   adj_col  = (const int*)d_in[1];
    const float* adj_vals = (const float*)d_in[2];
    const float* emb      = (const float*)d_in[3];
    const float* W1w      = (const float*)d_in[4];
    const float* W1b      = (const float*)d_in[5];
    const float* W2w      = (const float*)d_in[6];
    const float* W2b      = (const float*)d_in[7];
    float* out = (float*)d_out;

    cudaFuncSetAttribute(fused_layer_kernel, cudaFuncAttributeMaxDynamicSharedMemorySize, GEMM_SMEM);

    setup_kernel<<<(SETUP_N + 255) / 256, 256>>>(emb, out, W1w, W1b, W2w, W2b, adj_row);
    bsum_kernel<<<NBLK, 256>>>();
    bscan_kernel<<<1, 512>>>();
    pscan_kernel<<<NBLK, 256>>>();
    scatter_kernel<<<(NNZ + 255) / 256, 256>>>(adj_row, adj_col, adj_vals);

    // resolve device-global addresses for ping-pong x
    float* xa;
    float* xb;
    cudaGetSymbolAddress((void**)&xa, g_xa);
    cudaGetSymbolAddress((void**)&xb, g_xb);

    fused_layer_kernel<<<GEMM_GRID, 256, GEMM_SMEM>>>(xa, xb, out, 0);
    fused_layer_kernel<<<GEMM_GRID, 256, GEMM_SMEM>>>(xb, xa, out, 1);
}

// round 12
// speedup vs baseline: 2.1986x; 2.1986x over previous
#include <cuda_runtime.h>
#include <cuda_bf16.h>
#include <cuda_fp16.h>
#include <cstdint>

#define N_NODES 100000
#define DIM 128
#define NNZ 1600000
#define NBLK ((N_NODES + 255) / 256)    // 391 scan blocks
#define N_TILES ((N_NODES + 127) / 128) // 782 gemm tiles
#define GEMM_GRID 152                   // persistent blocks (GB300: 152 SMs)

// -------- device-global scratch (no allocations allowed) --------
__device__ float  g_x[(size_t)N_NODES * DIM];            // current layer embedding (f32)
__device__ __half g_xh[(size_t)N_NODES * DIM];           // fp16 shadow of x (for column gathers)
__device__ __nv_bfloat16 g_ah[(size_t)N_NODES * 256];    // A hi: [0:128)=side+x, [128:256)=side*x
__device__ __nv_bfloat16 g_al[(size_t)N_NODES * 256];    // A lo
__device__ __nv_bfloat16 g_wbh[2 * 256 * 128];           // pre-split weights hi, k-major [layer][k][n]
__device__ __nv_bfloat16 g_wbl[2 * 256 * 128];           // pre-split weights lo
__device__ float g_bias[2 * 128];                         // combined bias per layer
__device__ int   g_cnt[N_NODES];                          // CSR histogram (zeroed by pscan after use)
__device__ int   g_rank[NNZ];                             // within-row rank of each edge
__device__ int   g_bsum[NBLK];                            // per-block sums
__device__ int   g_boff[NBLK];                            // per-block exclusive offsets
__device__ int   g_ptr[N_NODES + 1];                      // CSR row pointers
__device__ int2  g_edge[NNZ];                             // packed (col, val) sorted by row

__device__ __forceinline__ void bf16_split(float v, __nv_bfloat16& h, __nv_bfloat16& l) {
    h = __float2bfloat16(v);
    l = __float2bfloat16(v - __bfloat162float(h));
}

// ================= fused setup: init-x/out + weight prep + histogram(+rank) =================
#define INIT_N (N_NODES * 32)           // 3,200,000 float4 copies
#define WP_N   (2 * 256 * 128)          // 65,536 weight elements
#define SETUP_N (INIT_N + WP_N + NNZ)

__global__ void __launch_bounds__(256) setup_kernel(const float* __restrict__ emb,
                                                    float* __restrict__ out,
                                                    const float* __restrict__ W1,
                                                    const float* __restrict__ b1,
                                                    const float* __restrict__ W2,
                                                    const float* __restrict__ b2,
                                                    const int* __restrict__ rows) {
    int t = blockIdx.x * blockDim.x + threadIdx.x;
    if (t < INIT_N) {                                  // ---- init ----
        int row = t >> 5, c = t & 31;
        float4 e = ((const float4*)emb)[t];
        ((float4*)g_x)[t] = e;
        __half2 h0 = __floats2half2_rn(e.x, e.y);
        __half2 h1 = __floats2half2_rn(e.z, e.w);
        ((uint2*)g_xh)[t] = make_uint2(*(uint32_t*)&h0, *(uint32_t*)&h1);
        ((float4*)out)[row * 96 + c] = e;
    } else if (t < INIT_N + WP_N) {                    // ---- weight prep ----
        int idx = t - INIT_N;
        int n = idx & 127;
        int k = (idx >> 7) & 255;
        int layer = idx >> 15;
        float w = (k < 128) ? W1[layer * 16384 + n * 128 + k]
                            : W2[layer * 16384 + n * 128 + (k - 128)];
        __nv_bfloat16 h, l;
        bf16_split(w, h, l);
        g_wbh[idx] = h;
        g_wbl[idx] = l;
        if (idx < 256) {
            int L = idx >> 7, nn = idx & 127;
            g_bias[idx] = b1[L * 128 + nn] + b2[L * 128 + nn];
        }
    } else if (t < SETUP_N) {                          // ---- histogram + rank ----
        int e = t - (INIT_N + WP_N);
        g_rank[e] = atomicAdd(&g_cnt[rows[e]], 1);
    }
}

// ================= CSR scan (3 phases) =================
__global__ void __launch_bounds__(256) bsum_kernel() {
    int g = blockIdx.x * 256 + threadIdx.x;
    int v = (g < N_NODES) ? g_cnt[g] : 0;
#pragma unroll
    for (int d = 16; d > 0; d >>= 1) v += __shfl_xor_sync(0xffffffffu, v, d);
    __shared__ int ws[8];
    if ((threadIdx.x & 31) == 0) ws[threadIdx.x >> 5] = v;
    __syncthreads();
    if (threadIdx.x == 0) {
        int s = 0;
#pragma unroll
        for (int i = 0; i < 8; i++) s += ws[i];
        g_bsum[blockIdx.x] = s;
    }
}

__global__ void __launch_bounds__(512) bscan_kernel() {
    int t = threadIdx.x;
    int lane = t & 31, warp = t >> 5;
    int v = (t < NBLK) ? g_bsum[t] : 0;
    int s = v;
#pragma unroll
    for (int d = 1; d < 32; d <<= 1) {
        int u = __shfl_up_sync(0xffffffffu, s, d);
        if (lane >= d) s += u;
    }
    __shared__ int ws[16];
    if (lane == 31) ws[warp] = s;
    __syncthreads();
    if (warp == 0) {                          // all 32 lanes shuffle
        int w = (lane < 16) ? ws[lane] : 0;
#pragma unroll
        for (int d = 1; d < 32; d <<= 1) {
            int u = __shfl_up_sync(0xffffffffu, w, d);
            if (lane >= d) w += u;
        }
        if (lane < 16) ws[lane] = w;
    }
    __syncthreads();
    int excl = s - v + (warp > 0 ? ws[warp - 1] : 0);
    if (t < NBLK) g_boff[t] = excl;
}

__global__ void __launch_bounds__(256) pscan_kernel() {
    int t = threadIdx.x;
    int lane = t & 31, warp = t >> 5;
    int g = blockIdx.x * 256 + t;
    int v = (g < N_NODES) ? g_cnt[g] : 0;
    int s = v;
#pragma unroll
    for (int d = 1; d < 32; d <<= 1) {
        int u = __shfl_up_sync(0xffffffffu, s, d);
        if (lane >= d) s += u;
    }
    __shared__ int ws[8];
    if (lane == 31) ws[warp] = s;
    __syncthreads();
    if (warp == 0) {                          // all 32 lanes shuffle
        int w = (lane < 8) ? ws[lane] : 0;
#pragma unroll
        for (int d = 1; d < 32; d <<= 1) {
            int u = __shfl_up_sync(0xffffffffu, w, d);
            if (lane >= d) w += u;
        }
        if (lane < 8) ws[lane] = w;
    }
    __syncthreads();
    int excl = s - v + (warp > 0 ? ws[warp - 1] : 0) + g_boff[blockIdx.x];
    if (g < N_NODES) {
        g_ptr[g] = excl;
        g_cnt[g] = 0;                         // reset for next graph replay
        if (g == N_NODES - 1) g_ptr[N_NODES] = NNZ;
    }
}

// atomic-free scatter using precomputed rank
__global__ void __launch_bounds__(256) scatter_kernel(const int* __restrict__ rows,
                                                      const int* __restrict__ cols,
                                                      const float* __restrict__ vals) {
    int e = blockIdx.x * blockDim.x + threadIdx.x;
    if (e >= NNZ) return;
    int pos = g_ptr[rows[e]] + g_rank[e];
    g_edge[pos] = make_int2(cols[e], __float_as_int(vals[e]));
}

// ================= gather SpMM (fp16 column reads) + fused bf16-split A generation =================
__global__ void __launch_bounds__(256) gather_kernel() {
    int gid  = blockIdx.x * blockDim.x + threadIdx.x;
    int r    = gid >> 5;
    int lane = gid & 31;
    if (r >= N_NODES) return;
    int n0 = g_ptr[r], n1 = g_ptr[r + 1];
    const uint2* gxh = (const uint2*)g_xh;   // 32 uint2 (128 halves) per row
    float4 acc = make_float4(0.f, 0.f, 0.f, 0.f);

    int e = n0;
    for (; e + 4 <= n1; e += 4) {
        int2 e0 = __ldg(&g_edge[e]),     e1 = __ldg(&g_edge[e + 1]);
        int2 e2 = __ldg(&g_edge[e + 2]), e3 = __ldg(&g_edge[e + 3]);
        uint2 p0 = gxh[(size_t)e0.x * 32 + lane];
        uint2 p1 = gxh[(size_t)e1.x * 32 + lane];
        uint2 p2 = gxh[(size_t)e2.x * 32 + lane];
        uint2 p3 = gxh[(size_t)e3.x * 32 + lane];
        float v0 = __int_as_float(e0.y), v1 = __int_as_float(e1.y);
        float v2 = __int_as_float(e2.y), v3 = __int_as_float(e3.y);
        float2 a0 = __half22float2(*(__half2*)&p0.x), b0 = __half22float2(*(__half2*)&p0.y);
        float2 a1 = __half22float2(*(__half2*)&p1.x), b1 = __half22float2(*(__half2*)&p1.y);
        float2 a2 = __half22float2(*(__half2*)&p2.x), b2 = __half22float2(*(__half2*)&p2.y);
        float2 a3 = __half22float2(*(__half2*)&p3.x), b3 = __half22float2(*(__half2*)&p3.y);
        acc.x = fmaf(v0, a0.x, acc.x); acc.y = fmaf(v0, a0.y, acc.y);
        acc.z = fmaf(v0, b0.x, acc.z); acc.w = fmaf(v0, b0.y, acc.w);
        acc.x = fmaf(v1, a1.x, acc.x); acc.y = fmaf(v1, a1.y, acc.y);
        acc.z = fmaf(v1, b1.x, acc.z); acc.w = fmaf(v1, b1.y, acc.w);
        acc.x = fmaf(v2, a2.x, acc.x); acc.y = fmaf(v2, a2.y, acc.y);
        acc.z = fmaf(v2, b2.x, acc.z); acc.w = fmaf(v2, b2.y, acc.w);
        acc.x = fmaf(v3, a3.x, acc.x); acc.y = fmaf(v3, a3.y, acc.y);
        acc.z = fmaf(v3, b3.x, acc.z); acc.w = fmaf(v3, b3.y, acc.w);
    }
    for (; e < n1; e++) {
        int2 ed = __ldg(&g_edge[e]);
        float v = __int_as_float(ed.y);
        uint2 p = gxh[(size_t)ed.x * 32 + lane];
        float2 a = __half22float2(*(__half2*)&p.x), b = __half22float2(*(__half2*)&p.y);
        acc.x = fmaf(v, a.x, acc.x); acc.y = fmaf(v, a.y, acc.y);
        acc.z = fmaf(v, b.x, acc.z); acc.w = fmaf(v, b.y, acc.w);
    }

    // self term from exact f32 x
    float4 xr = ((const float4*)g_x)[(size_t)r * 32 + lane];
    float a[4] = {acc.x + xr.x, acc.y + xr.y, acc.z + xr.z, acc.w + xr.w};
    float b[4] = {acc.x * xr.x, acc.y * xr.y, acc.z * xr.z, acc.w * xr.w};
    __nv_bfloat16 ha[4], la[4], hb[4], lb[4];
#pragma unroll
    for (int j = 0; j < 4; j++) { bf16_split(a[j], ha[j], la[j]); bf16_split(b[j], hb[j], lb[j]); }
    size_t base = (size_t)r * 256 + lane * 4;
    *(uint2*)(g_ah + base)        = *(uint2*)ha;
    *(uint2*)(g_ah + base + 128)  = *(uint2*)hb;
    *(uint2*)(g_al + base)        = *(uint2*)la;
    *(uint2*)(g_al + base + 128)  = *(uint2*)lb;
}

// ==================== mma.sync / cp.async helpers (baseline ISA) ====================
__device__ __forceinline__ uint32_t smem_u32(const void* p) {
    uint32_t a;
    asm("{ .reg .u64 t; cvta.to.shared.u64 t, %1; cvt.u32.u64 %0, t; }" : "=r"(a) : "l"(p));
    return a;
}
__device__ __forceinline__ void ldsm_x4(uint32_t* r, uint32_t addr) {
    asm volatile("ldmatrix.sync.aligned.m8n8.x4.shared.b16 {%0,%1,%2,%3}, [%4];"
                 : "=r"(r[0]), "=r"(r[1]), "=r"(r[2]), "=r"(r[3]) : "r"(addr));
}
__device__ __forceinline__ void ldsm_x4_t(uint32_t* r, uint32_t addr) {
    asm volatile("ldmatrix.sync.aligned.m8n8.x4.trans.shared.b16 {%0,%1,%2,%3}, [%4];"
                 : "=r"(r[0]), "=r"(r[1]), "=r"(r[2]), "=r"(r[3]) : "r"(addr));
}
__device__ __forceinline__ void mma_bf16(float* d, const uint32_t* a, const uint32_t* b) {
    asm volatile("mma.sync.aligned.m16n8k16.row.col.f32.bf16.bf16.f32 "
                 "{%0,%1,%2,%3}, {%4,%5,%6,%7}, {%8,%9}, {%0,%1,%2,%3};"
                 : "+f"(d[0]), "+f"(d[1]), "+f"(d[2]), "+f"(d[3])
                 : "r"(a[0]), "r"(a[1]), "r"(a[2]), "r"(a[3]), "r"(b[0]), "r"(b[1]));
}
__device__ __forceinline__ void cp16(uint32_t dst, const void* src, bool pred) {
    asm volatile("cp.async.cg.shared.global [%0], [%1], 16, %2;"
                 :: "r"(dst), "l"(src), "r"(pred ? 16u : 0u));
}
__device__ __forceinline__ void cp_commit() {
    asm volatile("cp.async.commit_group;" ::: "memory");
}

// ================= persistent pipelined bf16-split tensor-core dense layer =================
#define RSTRIDE_B 272
#define ASTRIDE 144
#define OFF_BH 0
#define OFF_BL (256 * RSTRIDE_B)                        // 69632
#define OFF_A  (2 * 256 * RSTRIDE_B)                    // 139264
#define ABUF(m, b) (OFF_A + (((b) * 2 + (m)) * 128 * ASTRIDE))
#define OFF_C  OFF_A                                    // 128*132*4 = 67584 <= 73728
#define GEMM_SMEM (OFF_A + 4 * 128 * ASTRIDE)           // 212992

__global__ void __launch_bounds__(256, 1) mma_gemm_kernel(float* __restrict__ out, int layer) {
    extern __shared__ char smem[];
    uint32_t sbase = smem_u32(smem);
    int tid = threadIdx.x;
    int wid = tid >> 5, lid = tid & 31;
    int warp_m = wid >> 2, warp_n = wid & 3;      // 2x4 warp grid: 64-row x 32-col warp tiles
    float4 bias4 = ((const float4*)(g_bias + layer * 128))[lid];

    // ---- stage B ONCE (cp.async; resident for all tiles) ----
    {
        const char* gwh = (const char*)g_wbh + (size_t)layer * 65536;
        const char* gwl = (const char*)g_wbl + (size_t)layer * 65536;
        for (int i = tid; i < 8192; i += 256) {
            int m = i >> 12, rem = i & 4095, r = rem >> 4, q = rem & 15;
            uint32_t dst = sbase + (m ? OFF_BL : OFF_BH) + r * RSTRIDE_B + q * 16;
            const char* src = (m ? gwl : gwh) + r * 256 + q * 16;
            cp16(dst, src, true);
        }
        cp_commit();
    }

    auto stageA = [&](int c, int row0) {
        int buf = c & 1;
        const char* gah = (const char*)g_ah;
        const char* gal = (const char*)g_al;
#pragma unroll
        for (int it = 0; it < 8; it++) {
            int i = tid + it * 256;                // 0..2047
            int m = i >> 10, rem = i & 1023, r = rem >> 3, q = rem & 7;
            int gr = row0 + r;
            uint32_t dst = sbase + ABUF(m, buf) + r * ASTRIDE + q * 16;
            const char* src = (m ? gal : gah) + (size_t)gr * 512 + c * 128 + q * 16;
            cp16(dst, src, gr < N_NODES);
        }
        cp_commit();
    };

    // ---- persistent tile loop ----
    for (int tile = blockIdx.x; tile < N_TILES; tile += gridDim.x) {
        int row0 = tile * 128;
        __syncthreads();                     // prev epilogue's Cs reads complete
        stageA(0, row0);
        stageA(1, row0);

        float acc[4][4][4];
#pragma unroll
        for (int mf = 0; mf < 4; mf++)
#pragma unroll
            for (int nf = 0; nf < 4; nf++)
#pragma unroll
                for (int q = 0; q < 4; q++) acc[mf][nf][q] = 0.f;

#pragma unroll
        for (int c = 0; c < 4; c++) {
            if (c < 3) asm volatile("cp.async.wait_group 1;" ::: "memory");
            else       asm volatile("cp.async.wait_group 0;" ::: "memory");
            __syncthreads();

            int buf = c & 1;
            int kb = c * 64;
#pragma unroll
            for (int k16 = 0; k16 < 4; k16++) {
                int k0 = k16 * 16;
                uint32_t ah[4][4], al[4][4];
                int ar = (lid & 15);
                int ac = (k0 + ((lid >> 4) << 3)) * 2;
#pragma unroll
                for (int mf = 0; mf < 4; mf++) {
                    int r = warp_m * 64 + mf * 16 + ar;
                    ldsm_x4(ah[mf], sbase + ABUF(0, buf) + r * ASTRIDE + ac);
                    ldsm_x4(al[mf], sbase + ABUF(1, buf) + r * ASTRIDE + ac);
                }
                uint32_t bh[4][2], bl[4][2];
                int br = kb + k0 + (lid & 15);
#pragma unroll
                for (int np = 0; np < 2; np++) {
                    int nc = (warp_n * 32 + np * 16 + ((lid >> 4) << 3)) * 2;
                    uint32_t t[4];
                    ldsm_x4_t(t, sbase + OFF_BH + br * RSTRIDE_B + nc);
                    bh[np * 2][0] = t[0]; bh[np * 2][1] = t[1];
                    bh[np * 2 + 1][0] = t[2]; bh[np * 2 + 1][1] = t[3];
                    ldsm_x4_t(t, sbase + OFF_BL + br * RSTRIDE_B + nc);
                    bl[np * 2][0] = t[0]; bl[np * 2][1] = t[1];
                    bl[np * 2 + 1][0] = t[2]; bl[np * 2 + 1][1] = t[3];
                }
#pragma unroll
                for (int mf = 0; mf < 4; mf++)
#pragma unroll
                    for (int nf = 0; nf < 4; nf++) {
                        mma_bf16(acc[mf][nf], ah[mf], bh[nf]);  // hi*hi
                        mma_bf16(acc[mf][nf], ah[mf], bl[nf]);  // hi*lo
                        mma_bf16(acc[mf][nf], al[mf], bh[nf]);  // lo*hi
                    }
            }
            __syncthreads();       // all ldmatrix reads of this buffer done
            if (c + 2 < 4) stageA(c + 2, row0);
        }

        // ---- dump accumulators to SMEM C tile (aliases A buf 0) ----
        float* Cs = (float*)(smem + OFF_C);
#pragma unroll
        for (int mf = 0; mf < 4; mf++)
#pragma unroll
            for (int nf = 0; nf < 4; nf++) {
                int r = warp_m * 64 + mf * 16 + (lid >> 2);
                int cc = warp_n * 32 + nf * 8 + (lid & 3) * 2;
                *(float2*)&Cs[r * 132 + cc]       = make_float2(acc[mf][nf][0], acc[mf][nf][1]);
                *(float2*)&Cs[(r + 8) * 132 + cc] = make_float2(acc[mf][nf][2], acc[mf][nf][3]);
            }
        __syncthreads();

        // ---- epilogue: warp per row — bias + leaky + L2 norm + dual store ----
#pragma unroll
        for (int it = 0; it < 16; it++) {
            int row = it * 8 + wid;
            int gr = row0 + row;
            float4 v = *(float4*)&Cs[row * 132 + lid * 4];
            float t0 = v.x + bias4.x, t1 = v.y + bias4.y;
            float t2 = v.z + bias4.z, t3 = v.w + bias4.w;
            t0 = (t0 > 0.f) ? t0 : 0.01f * t0;
            t1 = (t1 > 0.f) ? t1 : 0.01f * t1;
            t2 = (t2 > 0.f) ? t2 : 0.01f * t2;
            t3 = (t3 > 0.f) ? t3 : 0.01f * t3;
            float ss = fmaf(t0, t0, fmaf(t1, t1, fmaf(t2, t2, t3 * t3)));
            ss += __shfl_xor_sync(0xffffffffu, ss, 16);
            ss += __shfl_xor_sync(0xffffffffu, ss, 8);
            ss += __shfl_xor_sync(0xffffffffu, ss, 4);
            ss += __shfl_xor_sync(0xffffffffu, ss, 2);
            ss += __shfl_xor_sync(0xffffffffu, ss, 1);
            float sc = 1.0f / fmaxf(sqrtf(ss), 1e-12f);
            if (gr < N_NODES) {
                float4 o = make_float4(t0 * sc, t1 * sc, t2 * sc, t3 * sc);
                ((float4*)&g_x[(size_t)gr * 128])[lid] = o;
                ((float4*)&out[(size_t)gr * 384 + (size_t)(layer + 1) * 128])[lid] = o;
                if (layer == 0) {   // fp16 shadow only needed while another gather remains
                    __half2 h0 = __floats2half2_rn(o.x, o.y);
                    __half2 h1 = __floats2half2_rn(o.z, o.w);
                    ((uint2*)g_xh)[(size_t)gr * 32 + lid] = make_uint2(*(uint32_t*)&h0, *(uint32_t*)&h1);
                }
            }
        }
    }
}

// ================= launch =================
extern "C" void kernel_launch(void* const* d_in, const int* in_sizes, int n_in,
                              void* d_out, int out_size) {
    const int*   adj_row  = (const int*)d_in[0];
    const int*   adj_col  = (const int*)d_in[1];
    const float* adj_vals = (const float*)d_in[2];
    const float* emb      = (const float*)d_in[3];
    const float* W1w      = (const float*)d_in[4];
    const float* W1b      = (const float*)d_in[5];
    const float* W2w      = (const float*)d_in[6];
    const float* W2b      = (const float*)d_in[7];
    float* out = (float*)d_out;

    cudaFuncSetAttribute(mma_gemm_kernel, cudaFuncAttributeMaxDynamicSharedMemorySize, GEMM_SMEM);

    setup_kernel<<<(SETUP_N + 255) / 256, 256>>>(emb, out, W1w, W1b, W2w, W2b, adj_row);
    bsum_kernel<<<NBLK, 256>>>();
    bscan_kernel<<<1, 512>>>();
    pscan_kernel<<<NBLK, 256>>>();
    scatter_kernel<<<(NNZ + 255) / 256, 256>>>(adj_row, adj_col, adj_vals);

    const int gather_blocks = (N_NODES * 32 + 255) / 256;   // warp per row

    for (int layer = 0; layer < 2; layer++) {
        gather_kernel<<<gather_blocks, 256>>>();
        mma_gemm_kernel<<<GEMM_GRID, 256, GEMM_SMEM>>>(out, layer);
    }
}

// round 13
// speedup vs baseline: 2.5338x; 1.1525x over previous
#include <cuda_runtime.h>
#include <cuda_bf16.h>
#include <cuda_fp16.h>
#include <cstdint>

#define N_NODES 100000
#define DIM 128
#define NNZ 1600000
#define NBLK ((N_NODES + 255) / 256)    // 391 scan blocks
#define N_TILES ((N_NODES + 127) / 128) // 782 gemm tiles
#define GEMM_GRID 152                   // persistent blocks (GB300: 152 SMs)

// -------- device-global scratch (no allocations allowed) --------
__device__ float  g_x[(size_t)N_NODES * DIM];            // current layer embedding (f32)
__device__ __half g_xh[(size_t)N_NODES * DIM];           // fp16 shadow of x (column gathers)
__device__ __half g_af[(size_t)N_NODES * 256];           // A fp16: [0:128)=side+x, [128:256)=side*x
__device__ __half g_wfh[2 * 256 * 128];                  // weights fp16 hi, k-major [layer][k][n]
__device__ __half g_wfl[2 * 256 * 128];                  // weights fp16 lo (w - hi)
__device__ float g_bias[2 * 128];                         // combined bias per layer
__device__ int   g_cnt[N_NODES];                          // CSR histogram (zeroed by pscan after use)
__device__ int   g_rank[NNZ];                             // within-row rank of each edge
__device__ int   g_bsum[NBLK];                            // per-block sums
__device__ int   g_ptr[N_NODES + 1];                      // CSR row pointers
__device__ int2  g_edge[NNZ];                             // packed (col, val) sorted by row

__device__ __forceinline__ void fp16_split(float v, __half& h, __half& l) {
    h = __float2half(v);
    l = __float2half(v - __half2float(h));
}

// ================= fused setup: init-x/out + weight prep + histogram(+rank) =================
#define INIT_N (N_NODES * 32)           // 3,200,000 float4 copies
#define WP_N   (2 * 256 * 128)          // 65,536 weight elements
#define SETUP_N (INIT_N + WP_N + NNZ)

__global__ void __launch_bounds__(256) setup_kernel(const float* __restrict__ emb,
                                                    float* __restrict__ out,
                                                    const float* __restrict__ W1,
                                                    const float* __restrict__ b1,
                                                    const float* __restrict__ W2,
                                                    const float* __restrict__ b2,
                                                    const int* __restrict__ rows) {
    int t = blockIdx.x * blockDim.x + threadIdx.x;
    if (t < INIT_N) {                                  // ---- init ----
        int row = t >> 5, c = t & 31;
        float4 e = ((const float4*)emb)[t];
        ((float4*)g_x)[t] = e;
        __half2 h0 = __floats2half2_rn(e.x, e.y);
        __half2 h1 = __floats2half2_rn(e.z, e.w);
        ((uint2*)g_xh)[t] = make_uint2(*(uint32_t*)&h0, *(uint32_t*)&h1);
        ((float4*)out)[row * 96 + c] = e;
    } else if (t < INIT_N + WP_N) {                    // ---- weight prep (fp16 hi/lo) ----
        int idx = t - INIT_N;
        int n = idx & 127;
        int k = (idx >> 7) & 255;
        int layer = idx >> 15;
        float w = (k < 128) ? W1[layer * 16384 + n * 128 + k]
                            : W2[layer * 16384 + n * 128 + (k - 128)];
        __half h, l;
        fp16_split(w, h, l);
        g_wfh[idx] = h;
        g_wfl[idx] = l;
        if (idx < 256) {
            int L = idx >> 7, nn = idx & 127;
            g_bias[idx] = b1[L * 128 + nn] + b2[L * 128 + nn];
        }
    } else if (t < SETUP_N) {                          // ---- histogram + rank ----
        int e = t - (INIT_N + WP_N);
        g_rank[e] = atomicAdd(&g_cnt[rows[e]], 1);
    }
}

// ================= CSR scan (2 phases: bsum, then fused bscan+pscan) =================
__global__ void __launch_bounds__(256) bsum_kernel() {
    int g = blockIdx.x * 256 + threadIdx.x;
    int v = (g < N_NODES) ? g_cnt[g] : 0;
#pragma unroll
    for (int d = 16; d > 0; d >>= 1) v += __shfl_xor_sync(0xffffffffu, v, d);
    __shared__ int ws[8];
    if ((threadIdx.x & 31) == 0) ws[threadIdx.x >> 5] = v;
    __syncthreads();
    if (threadIdx.x == 0) {
        int s = 0;
#pragma unroll
        for (int i = 0; i < 8; i++) s += ws[i];
        g_bsum[blockIdx.x] = s;
    }
}

// fused: block offset = Σ g_bsum[0..bid) computed locally; then block-local scan
__global__ void __launch_bounds__(256) pscan_kernel() {
    int t = threadIdx.x;
    int lane = t & 31, warp = t >> 5;
    __shared__ int s_boff;
    __shared__ int ws[8];

    // ---- block offset: strided sum over g_bsum[0..bid) ----
    {
        int s = 0;
        for (int i = t; i < blockIdx.x; i += 256) s += g_bsum[i];
#pragma unroll
        for (int d = 16; d > 0; d >>= 1) s += __shfl_xor_sync(0xffffffffu, s, d);
        if (lane == 0) ws[warp] = s;
        __syncthreads();
        if (t == 0) {
            int tot = 0;
#pragma unroll
            for (int i = 0; i < 8; i++) tot += ws[i];
            s_boff = tot;
        }
        __syncthreads();
    }

    int g = blockIdx.x * 256 + t;
    int v = (g < N_NODES) ? g_cnt[g] : 0;
    int s = v;
#pragma unroll
    for (int d = 1; d < 32; d <<= 1) {
        int u = __shfl_up_sync(0xffffffffu, s, d);
        if (lane >= d) s += u;
    }
    if (lane == 31) ws[warp] = s;
    __syncthreads();
    if (warp == 0) {                          // all 32 lanes shuffle
        int w = (lane < 8) ? ws[lane] : 0;
#pragma unroll
        for (int d = 1; d < 32; d <<= 1) {
            int u = __shfl_up_sync(0xffffffffu, w, d);
            if (lane >= d) w += u;
        }
        if (lane < 8) ws[lane] = w;
    }
    __syncthreads();
    int excl = s - v + (warp > 0 ? ws[warp - 1] : 0) + s_boff;
    if (g < N_NODES) {
        g_ptr[g] = excl;
        g_cnt[g] = 0;                         // reset for next graph replay
        if (g == N_NODES - 1) g_ptr[N_NODES] = NNZ;
    }
}

// atomic-free scatter using precomputed rank
__global__ void __launch_bounds__(256) scatter_kernel(const int* __restrict__ rows,
                                                      const int* __restrict__ cols,
                                                      const float* __restrict__ vals) {
    int e = blockIdx.x * blockDim.x + threadIdx.x;
    if (e >= NNZ) return;
    int pos = g_ptr[rows[e]] + g_rank[e];
    g_edge[pos] = make_int2(cols[e], __float_as_int(vals[e]));
}

// ================= gather SpMM (fp16 columns) -> fp16 A =================
__global__ void __launch_bounds__(256) gather_kernel() {
    int gid  = blockIdx.x * blockDim.x + threadIdx.x;
    int r    = gid >> 5;
    int lane = gid & 31;
    if (r >= N_NODES) return;
    int n0 = g_ptr[r], n1 = g_ptr[r + 1];
    const uint2* gxh = (const uint2*)g_xh;   // 32 uint2 (128 halves) per row
    float4 acc = make_float4(0.f, 0.f, 0.f, 0.f);

    int e = n0;
    for (; e + 4 <= n1; e += 4) {
        int2 e0 = __ldg(&g_edge[e]),     e1 = __ldg(&g_edge[e + 1]);
        int2 e2 = __ldg(&g_edge[e + 2]), e3 = __ldg(&g_edge[e + 3]);
        uint2 p0 = gxh[(size_t)e0.x * 32 + lane];
        uint2 p1 = gxh[(size_t)e1.x * 32 + lane];
        uint2 p2 = gxh[(size_t)e2.x * 32 + lane];
        uint2 p3 = gxh[(size_t)e3.x * 32 + lane];
        float v0 = __int_as_float(e0.y), v1 = __int_as_float(e1.y);
        float v2 = __int_as_float(e2.y), v3 = __int_as_float(e3.y);
        float2 a0 = __half22float2(*(__half2*)&p0.x), b0 = __half22float2(*(__half2*)&p0.y);
        float2 a1 = __half22float2(*(__half2*)&p1.x), b1 = __half22float2(*(__half2*)&p1.y);
        float2 a2 = __half22float2(*(__half2*)&p2.x), b2 = __half22float2(*(__half2*)&p2.y);
        float2 a3 = __half22float2(*(__half2*)&p3.x), b3 = __half22float2(*(__half2*)&p3.y);
        acc.x = fmaf(v0, a0.x, acc.x); acc.y = fmaf(v0, a0.y, acc.y);
        acc.z = fmaf(v0, b0.x, acc.z); acc.w = fmaf(v0, b0.y, acc.w);
        acc.x = fmaf(v1, a1.x, acc.x); acc.y = fmaf(v1, a1.y, acc.y);
        acc.z = fmaf(v1, b1.x, acc.z); acc.w = fmaf(v1, b1.y, acc.w);
        acc.x = fmaf(v2, a2.x, acc.x); acc.y = fmaf(v2, a2.y, acc.y);
        acc.z = fmaf(v2, b2.x, acc.z); acc.w = fmaf(v2, b2.y, acc.w);
        acc.x = fmaf(v3, a3.x, acc.x); acc.y = fmaf(v3, a3.y, acc.y);
        acc.z = fmaf(v3, b3.x, acc.z); acc.w = fmaf(v3, b3.y, acc.w);
    }
    for (; e < n1; e++) {
        int2 ed = __ldg(&g_edge[e]);
        float v = __int_as_float(ed.y);
        uint2 p = gxh[(size_t)ed.x * 32 + lane];
        float2 a = __half22float2(*(__half2*)&p.x), b = __half22float2(*(__half2*)&p.y);
        acc.x = fmaf(v, a.x, acc.x); acc.y = fmaf(v, a.y, acc.y);
        acc.z = fmaf(v, b.x, acc.z); acc.w = fmaf(v, b.y, acc.w);
    }

    // self term from exact f32 x (streamed once per row)
    float4 xr = ((const float4*)g_x)[(size_t)r * 32 + lane];
    __half2 ha0 = __floats2half2_rn(acc.x + xr.x, acc.y + xr.y);
    __half2 ha1 = __floats2half2_rn(acc.z + xr.z, acc.w + xr.w);
    __half2 hb0 = __floats2half2_rn(acc.x * xr.x, acc.y * xr.y);
    __half2 hb1 = __floats2half2_rn(acc.z * xr.z, acc.w * xr.w);
    size_t base = (size_t)r * 256 + lane * 4;
    *(uint2*)(g_af + base)       = make_uint2(*(uint32_t*)&ha0, *(uint32_t*)&ha1);
    *(uint2*)(g_af + base + 128) = make_uint2(*(uint32_t*)&hb0, *(uint32_t*)&hb1);
}

// ==================== mma.sync / cp.async helpers (baseline ISA) ====================
__device__ __forceinline__ uint32_t smem_u32(const void* p) {
    uint32_t a;
    asm("{ .reg .u64 t; cvta.to.shared.u64 t, %1; cvt.u32.u64 %0, t; }" : "=r"(a) : "l"(p));
    return a;
}
__device__ __forceinline__ void ldsm_x4(uint32_t* r, uint32_t addr) {
    asm volatile("ldmatrix.sync.aligned.m8n8.x4.shared.b16 {%0,%1,%2,%3}, [%4];"
                 : "=r"(r[0]), "=r"(r[1]), "=r"(r[2]), "=r"(r[3]) : "r"(addr));
}
__device__ __forceinline__ void ldsm_x4_t(uint32_t* r, uint32_t addr) {
    asm volatile("ldmatrix.sync.aligned.m8n8.x4.trans.shared.b16 {%0,%1,%2,%3}, [%4];"
                 : "=r"(r[0]), "=r"(r[1]), "=r"(r[2]), "=r"(r[3]) : "r"(addr));
}
__device__ __forceinline__ void mma_f16(float* d, const uint32_t* a, const uint32_t* b) {
    asm volatile("mma.sync.aligned.m16n8k16.row.col.f32.f16.f16.f32 "
                 "{%0,%1,%2,%3}, {%4,%5,%6,%7}, {%8,%9}, {%0,%1,%2,%3};"
                 : "+f"(d[0]), "+f"(d[1]), "+f"(d[2]), "+f"(d[3])
                 : "r"(a[0]), "r"(a[1]), "r"(a[2]), "r"(a[3]), "r"(b[0]), "r"(b[1]));
}
__device__ __forceinline__ void cp16(uint32_t dst, const void* src, bool pred) {
    asm volatile("cp.async.cg.shared.global [%0], [%1], 16, %2;"
                 :: "r"(dst), "l"(src), "r"(pred ? 16u : 0u));
}
__device__ __forceinline__ void cp_commit() {
    asm volatile("cp.async.commit_group;" ::: "memory");
}

// ================= persistent pipelined fp16 tensor-core dense layer =================
// A fp16 single; W fp16 hi/lo; D = A*(Wh + Wl), 2 MMAs per fragment pair.
#define RSTRIDE_B 272
#define ASTRIDE 144
#define OFF_BH 0
#define OFF_BL (256 * RSTRIDE_B)                        // 69632
#define OFF_A  (2 * 256 * RSTRIDE_B)                    // 139264
#define ABUF(b) (OFF_A + (b) * 128 * ASTRIDE)           // 2 x 18432
#define OFF_C  OFF_A                                    // C tile 128*132*4 = 67584
#define GEMM_SMEM (OFF_A + 67584)                       // 206848

__global__ void __launch_bounds__(256, 1) mma_gemm_kernel(float* __restrict__ out, int layer) {
    extern __shared__ char smem[];
    uint32_t sbase = smem_u32(smem);
    int tid = threadIdx.x;
    int wid = tid >> 5, lid = tid & 31;
    int warp_m = wid >> 2, warp_n = wid & 3;      // 2x4 warp grid: 64-row x 32-col warp tiles
    float4 bias4 = ((const float4*)(g_bias + layer * 128))[lid];

    // ---- stage B ONCE (cp.async; resident for all tiles) ----
    {
        const char* gwh = (const char*)g_wfh + (size_t)layer * 65536;
        const char* gwl = (const char*)g_wfl + (size_t)layer * 65536;
        for (int i = tid; i < 8192; i += 256) {
            int m = i >> 12, rem = i & 4095, r = rem >> 4, q = rem & 15;
            uint32_t dst = sbase + (m ? OFF_BL : OFF_BH) + r * RSTRIDE_B + q * 16;
            const char* src = (m ? gwl : gwh) + r * 256 + q * 16;
            cp16(dst, src, true);
        }
        cp_commit();
    }

    // A chunk staging: chunk c = 128 rows x 128 bytes (64 fp16 of k)
    auto stageA = [&](int c, int row0) {
        int buf = c & 1;
        const char* gaf = (const char*)g_af;
#pragma unroll
        for (int it = 0; it < 4; it++) {
            int i = tid + it * 256;                // 0..1023
            int r = i >> 3, q = i & 7;
            int gr = row0 + r;
            uint32_t dst = sbase + ABUF(buf) + r * ASTRIDE + q * 16;
            const char* src = gaf + (size_t)gr * 512 + c * 128 + q * 16;
            cp16(dst, src, gr < N_NODES);
        }
        cp_commit();
    };

    // ---- persistent tile loop ----
    for (int tile = blockIdx.x; tile < N_TILES; tile += gridDim.x) {
        int row0 = tile * 128;
        __syncthreads();                     // prev epilogue's Cs reads complete
        stageA(0, row0);
        stageA(1, row0);

        float acc[4][4][4];
#pragma unroll
        for (int mf = 0; mf < 4; mf++)
#pragma unroll
            for (int nf = 0; nf < 4; nf++)
#pragma unroll
                for (int q = 0; q < 4; q++) acc[mf][nf][q] = 0.f;

#pragma unroll
        for (int c = 0; c < 4; c++) {
            if (c < 3) asm volatile("cp.async.wait_group 1;" ::: "memory");
            else       asm volatile("cp.async.wait_group 0;" ::: "memory");
            __syncthreads();

            int buf = c & 1;
            int kb = c * 64;
#pragma unroll
            for (int k16 = 0; k16 < 4; k16++) {
                int k0 = k16 * 16;
                uint32_t ah[4][4];
                int ar = (lid & 15);
                int ac = (k0 + ((lid >> 4) << 3)) * 2;
#pragma unroll
                for (int mf = 0; mf < 4; mf++) {
                    int r = warp_m * 64 + mf * 16 + ar;
                    ldsm_x4(ah[mf], sbase + ABUF(buf) + r * ASTRIDE + ac);
                }
                uint32_t bh[4][2], bl[4][2];
                int br = kb + k0 + (lid & 15);
#pragma unroll
                for (int np = 0; np < 2; np++) {
                    int nc = (warp_n * 32 + np * 16 + ((lid >> 4) << 3)) * 2;
                    uint32_t t[4];
                    ldsm_x4_t(t, sbase + OFF_BH + br * RSTRIDE_B + nc);
                    bh[np * 2][0] = t[0]; bh[np * 2][1] = t[1];
                    bh[np * 2 + 1][0] = t[2]; bh[np * 2 + 1][1] = t[3];
                    ldsm_x4_t(t, sbase + OFF_BL + br * RSTRIDE_B + nc);
                    bl[np * 2][0] = t[0]; bl[np * 2][1] = t[1];
                    bl[np * 2 + 1][0] = t[2]; bl[np * 2 + 1][1] = t[3];
                }
#pragma unroll
                for (int mf = 0; mf < 4; mf++)
#pragma unroll
                    for (int nf = 0; nf < 4; nf++) {
                        mma_f16(acc[mf][nf], ah[mf], bh[nf]);  // A * Whi
                        mma_f16(acc[mf][nf], ah[mf], bl[nf]);  // A * Wlo
                    }
            }
            __syncthreads();       // all ldmatrix reads of this buffer done
            if (c + 2 < 4) stageA(c + 2, row0);
        }

        // ---- dump accumulators to SMEM C tile (aliases A region) ----
        float* Cs = (float*)(smem + OFF_C);
#pragma unroll
        for (int mf = 0; mf < 4; mf++)
#pragma unroll
            for (int nf = 0; nf < 4; nf++) {
                int r = warp_m * 64 + mf * 16 + (lid >> 2);
                int cc = warp_n * 32 + nf * 8 + (lid & 3) * 2;
                *(float2*)&Cs[r * 132 + cc]       = make_float2(acc[mf][nf][0], acc[mf][nf][1]);
                *(float2*)&Cs[(r + 8) * 132 + cc] = make_float2(acc[mf][nf][2], acc[mf][nf][3]);
            }
        __syncthreads();

        // ---- epilogue: warp per row — bias + leaky + L2 norm + dual store ----
#pragma unroll
        for (int it = 0; it < 16; it++) {
            int row = it * 8 + wid;
            int gr = row0 + row;
            float4 v = *(float4*)&Cs[row * 132 + lid * 4];
            float t0 = v.x + bias4.x, t1 = v.y + bias4.y;
            float t2 = v.z + bias4.z, t3 = v.w + bias4.w;
            t0 = (t0 > 0.f) ? t0 : 0.01f * t0;
            t1 = (t1 > 0.f) ? t1 : 0.01f * t1;
            t2 = (t2 > 0.f) ? t2 : 0.01f * t2;
            t3 = (t3 > 0.f) ? t3 : 0.01f * t3;
            float ss = fmaf(t0, t0, fmaf(t1, t1, fmaf(t2, t2, t3 * t3)));
            ss += __shfl_xor_sync(0xffffffffu, ss, 16);
            ss += __shfl_xor_sync(0xffffffffu, ss, 8);
            ss += __shfl_xor_sync(0xffffffffu, ss, 4);
            ss += __shfl_xor_sync(0xffffffffu, ss, 2);
            ss += __shfl_xor_sync(0xffffffffu, ss, 1);
            float sc = 1.0f / fmaxf(sqrtf(ss), 1e-12f);
            if (gr < N_NODES) {
                float4 o = make_float4(t0 * sc, t1 * sc, t2 * sc, t3 * sc);
                ((float4*)&g_x[(size_t)gr * 128])[lid] = o;
                ((float4*)&out[(size_t)gr * 384 + (size_t)(layer + 1) * 128])[lid] = o;
                if (layer == 0) {   // fp16 shadow only needed while another gather remains
                    __half2 h0 = __floats2half2_rn(o.x, o.y);
                    __half2 h1 = __floats2half2_rn(o.z, o.w);
                    ((uint2*)g_xh)[(size_t)gr * 32 + lid] = make_uint2(*(uint32_t*)&h0, *(uint32_t*)&h1);
                }
            }
        }
    }
}

// ================= launch =================
extern "C" void kernel_launch(void* const* d_in, const int* in_sizes, int n_in,
                              void* d_out, int out_size) {
    const int*   adj_row  = (const int*)d_in[0];
    const int*   adj_col  = (const int*)d_in[1];
    const float* adj_vals = (const float*)d_in[2];
    const float* emb      = (const float*)d_in[3];
    const float* W1w      = (const float*)d_in[4];
    const float* W1b      = (const float*)d_in[5];
    const float* W2w      = (const float*)d_in[6];
    const float* W2b      = (const float*)d_in[7];
    float* out = (float*)d_out;

    cudaFuncSetAttribute(mma_gemm_kernel, cudaFuncAttributeMaxDynamicSharedMemorySize, GEMM_SMEM);

    setup_kernel<<<(SETUP_N + 255) / 256, 256>>>(emb, out, W1w, W1b, W2w, W2b, adj_row);
    bsum_kernel<<<NBLK, 256>>>();
    pscan_kernel<<<NBLK, 256>>>();
    scatter_kernel<<<(NNZ + 255) / 256, 256>>>(adj_row, adj_col, adj_vals);

    const int gather_blocks = (N_NODES * 32 + 255) / 256;   // warp per row

    for (int layer = 0; layer < 2; layer++) {
        gather_kernel<<<gather_blocks, 256>>>();
        mma_gemm_kernel<<<GEMM_GRID, 256, GEMM_SMEM>>>(out, layer);
    }
}

// round 14
// speedup vs baseline: 2.5344x; 1.0002x over previous
#include <cuda_runtime.h>
#include <cuda_bf16.h>
#include <cuda_fp16.h>
#include <cstdint>

#define N_NODES 100000
#define DIM 128
#define NNZ 1600000
#define NBLK ((N_NODES + 255) / 256)    // 391 scan blocks
#define N_TILES ((N_NODES + 127) / 128) // 782 gemm tiles
#define GEMM_GRID 152                   // persistent blocks (GB300: 152 SMs)
#define GATHER_BLOCKS (N_NODES / 8)     // 12500 (8 rows per block, exact)

// -------- device-global scratch (no allocations allowed) --------
__device__ __half g_xha[(size_t)N_NODES * DIM];          // fp16 x ping
__device__ __half g_xhb[(size_t)N_NODES * DIM];          // fp16 x pong
__device__ __half g_af[(size_t)N_NODES * 256];           // A fp16: [0:128)=side+x, [128:256)=side*x
__device__ __half g_wfh[2 * 256 * 128];                  // weights fp16 hi, k-major [layer][k][n]
__device__ __half g_wfl[2 * 256 * 128];                  // weights fp16 lo (w - hi)
__device__ float g_bias[2 * 128];                         // combined bias per layer
__device__ unsigned g_tilecnt[N_TILES];                   // producer-consumer flags (self-resetting)
__device__ int   g_cnt[N_NODES];                          // CSR histogram (zeroed by pscan after use)
__device__ int   g_rank[NNZ];                             // within-row rank of each edge
__device__ int   g_bsum[NBLK];                            // per-block sums
__device__ int   g_ptr[N_NODES + 1];                      // CSR row pointers
__device__ int2  g_edge[NNZ];                             // packed (col, val) sorted by row

__device__ __forceinline__ void fp16_split(float v, __half& h, __half& l) {
    h = __float2half(v);
    l = __float2half(v - __half2float(h));
}

// ================= fused setup: init-xh/out + weight prep + histogram(+rank) =================
#define INIT_N (N_NODES * 32)           // 3,200,000 float4 reads of emb
#define WP_N   (2 * 256 * 128)          // 65,536 weight elements
#define SETUP_N (INIT_N + WP_N + NNZ)

__global__ void __launch_bounds__(256) setup_kernel(const float* __restrict__ emb,
                                                    float* __restrict__ out,
                                                    const float* __restrict__ W1,
                                                    const float* __restrict__ b1,
                                                    const float* __restrict__ W2,
                                                    const float* __restrict__ b2,
                                                    const int* __restrict__ rows) {
    int t = blockIdx.x * blockDim.x + threadIdx.x;
    if (t < INIT_N) {                                  // ---- init ----
        int row = t >> 5, c = t & 31;
        float4 e = ((const float4*)emb)[t];
        __half2 h0 = __floats2half2_rn(e.x, e.y);
        __half2 h1 = __floats2half2_rn(e.z, e.w);
        ((uint2*)g_xha)[t] = make_uint2(*(uint32_t*)&h0, *(uint32_t*)&h1);
        ((float4*)out)[row * 96 + c] = e;
    } else if (t < INIT_N + WP_N) {                    // ---- weight prep (fp16 hi/lo) ----
        int idx = t - INIT_N;
        int n = idx & 127;
        int k = (idx >> 7) & 255;
        int layer = idx >> 15;
        float w = (k < 128) ? W1[layer * 16384 + n * 128 + k]
                            : W2[layer * 16384 + n * 128 + (k - 128)];
        __half h, l;
        fp16_split(w, h, l);
        g_wfh[idx] = h;
        g_wfl[idx] = l;
        if (idx < 256) {
            int L = idx >> 7, nn = idx & 127;
            g_bias[idx] = b1[L * 128 + nn] + b2[L * 128 + nn];
        }
    } else if (t < SETUP_N) {                          // ---- histogram + rank ----
        int e = t - (INIT_N + WP_N);
        g_rank[e] = atomicAdd(&g_cnt[rows[e]], 1);
    }
}

// ================= CSR scan (bsum, then fused bscan+pscan) =================
__global__ void __launch_bounds__(256) bsum_kernel() {
    int g = blockIdx.x * 256 + threadIdx.x;
    int v = (g < N_NODES) ? g_cnt[g] : 0;
#pragma unroll
    for (int d = 16; d > 0; d >>= 1) v += __shfl_xor_sync(0xffffffffu, v, d);
    __shared__ int ws[8];
    if ((threadIdx.x & 31) == 0) ws[threadIdx.x >> 5] = v;
    __syncthreads();
    if (threadIdx.x == 0) {
        int s = 0;
#pragma unroll
        for (int i = 0; i < 8; i++) s += ws[i];
        g_bsum[blockIdx.x] = s;
    }
}

__global__ void __launch_bounds__(256) pscan_kernel() {
    int t = threadIdx.x;
    int lane = t & 31, warp = t >> 5;
    __shared__ int s_boff;
    __shared__ int ws[8];
    {
        int s = 0;
        for (int i = t; i < blockIdx.x; i += 256) s += g_bsum[i];
#pragma unroll
        for (int d = 16; d > 0; d >>= 1) s += __shfl_xor_sync(0xffffffffu, s, d);
        if (lane == 0) ws[warp] = s;
        __syncthreads();
        if (t == 0) {
            int tot = 0;
#pragma unroll
            for (int i = 0; i < 8; i++) tot += ws[i];
            s_boff = tot;
        }
        __syncthreads();
    }
    int g = blockIdx.x * 256 + t;
    int v = (g < N_NODES) ? g_cnt[g] : 0;
    int s = v;
#pragma unroll
    for (int d = 1; d < 32; d <<= 1) {
        int u = __shfl_up_sync(0xffffffffu, s, d);
        if (lane >= d) s += u;
    }
    if (lane == 31) ws[warp] = s;
    __syncthreads();
    if (warp == 0) {
        int w = (lane < 8) ? ws[lane] : 0;
#pragma unroll
        for (int d = 1; d < 32; d <<= 1) {
            int u = __shfl_up_sync(0xffffffffu, w, d);
            if (lane >= d) w += u;
        }
        if (lane < 8) ws[lane] = w;
    }
    __syncthreads();
    int excl = s - v + (warp > 0 ? ws[warp - 1] : 0) + s_boff;
    if (g < N_NODES) {
        g_ptr[g] = excl;
        g_cnt[g] = 0;                         // reset for next graph replay
        if (g == N_NODES - 1) g_ptr[N_NODES] = NNZ;
    }
}

__global__ void __launch_bounds__(256) scatter_kernel(const int* __restrict__ rows,
                                                      const int* __restrict__ cols,
                                                      const float* __restrict__ vals) {
    int e = blockIdx.x * blockDim.x + threadIdx.x;
    if (e >= NNZ) return;
    int pos = g_ptr[rows[e]] + g_rank[e];
    g_edge[pos] = make_int2(cols[e], __float_as_int(vals[e]));
}

// ================= gather SpMM producer: warp-per-row -> fp16 A + tile flags =================
__global__ void __launch_bounds__(256) gather_kernel(const __half* __restrict__ xsrc) {
    int r = blockIdx.x * 8 + (threadIdx.x >> 5);   // 8 rows per block, all valid
    int lane = threadIdx.x & 31;
    int n0 = g_ptr[r], n1 = g_ptr[r + 1];
    const uint2* gxh = (const uint2*)xsrc;
    float4 acc = make_float4(0.f, 0.f, 0.f, 0.f);

    int e = n0;
    for (; e + 4 <= n1; e += 4) {
        int2 e0 = __ldg(&g_edge[e]),     e1 = __ldg(&g_edge[e + 1]);
        int2 e2 = __ldg(&g_edge[e + 2]), e3 = __ldg(&g_edge[e + 3]);
        uint2 p0 = gxh[(size_t)e0.x * 32 + lane];
        uint2 p1 = gxh[(size_t)e1.x * 32 + lane];
        uint2 p2 = gxh[(size_t)e2.x * 32 + lane];
        uint2 p3 = gxh[(size_t)e3.x * 32 + lane];
        float v0 = __int_as_float(e0.y), v1 = __int_as_float(e1.y);
        float v2 = __int_as_float(e2.y), v3 = __int_as_float(e3.y);
        float2 a0 = __half22float2(*(__half2*)&p0.x), b0 = __half22float2(*(__half2*)&p0.y);
        float2 a1 = __half22float2(*(__half2*)&p1.x), b1 = __half22float2(*(__half2*)&p1.y);
        float2 a2 = __half22float2(*(__half2*)&p2.x), b2 = __half22float2(*(__half2*)&p2.y);
        float2 a3 = __half22float2(*(__half2*)&p3.x), b3 = __half22float2(*(__half2*)&p3.y);
        acc.x = fmaf(v0, a0.x, acc.x); acc.y = fmaf(v0, a0.y, acc.y);
        acc.z = fmaf(v0, b0.x, acc.z); acc.w = fmaf(v0, b0.y, acc.w);
        acc.x = fmaf(v1, a1.x, acc.x); acc.y = fmaf(v1, a1.y, acc.y);
        acc.z = fmaf(v1, b1.x, acc.z); acc.w = fmaf(v1, b1.y, acc.w);
        acc.x = fmaf(v2, a2.x, acc.x); acc.y = fmaf(v2, a2.y, acc.y);
        acc.z = fmaf(v2, b2.x, acc.z); acc.w = fmaf(v2, b2.y, acc.w);
        acc.x = fmaf(v3, a3.x, acc.x); acc.y = fmaf(v3, a3.y, acc.y);
        acc.z = fmaf(v3, b3.x, acc.z); acc.w = fmaf(v3, b3.y, acc.w);
    }
    for (; e < n1; e++) {
        int2 ed = __ldg(&g_edge[e]);
        float v = __int_as_float(ed.y);
        uint2 p = gxh[(size_t)ed.x * 32 + lane];
        float2 a = __half22float2(*(__half2*)&p.x), b = __half22float2(*(__half2*)&p.y);
        acc.x = fmaf(v, a.x, acc.x); acc.y = fmaf(v, a.y, acc.y);
        acc.z = fmaf(v, b.x, acc.z); acc.w = fmaf(v, b.y, acc.w);
    }

    // self term from fp16 x
    uint2 pr = gxh[(size_t)r * 32 + lane];
    float2 xr0 = __half22float2(*(__half2*)&pr.x);
    float2 xr1 = __half22float2(*(__half2*)&pr.y);
    __half2 ha0 = __floats2half2_rn(acc.x + xr0.x, acc.y + xr0.y);
    __half2 ha1 = __floats2half2_rn(acc.z + xr1.x, acc.w + xr1.y);
    __half2 hb0 = __floats2half2_rn(acc.x * xr0.x, acc.y * xr0.y);
    __half2 hb1 = __floats2half2_rn(acc.z * xr1.x, acc.w * xr1.y);
    size_t base = (size_t)r * 256 + lane * 4;
    *(uint2*)(g_af + base)       = make_uint2(*(uint32_t*)&ha0, *(uint32_t*)&ha1);
    *(uint2*)(g_af + base + 128) = make_uint2(*(uint32_t*)&hb0, *(uint32_t*)&hb1);

    // signal: this block's 8 rows of tile (bid>>4) are done
    __syncthreads();
    __threadfence();
    if (threadIdx.x == 0) atomicAdd(&g_tilecnt[blockIdx.x >> 4], 1u);
}

// ==================== mma.sync / cp.async helpers (baseline ISA) ====================
__device__ __forceinline__ uint32_t smem_u32(const void* p) {
    uint32_t a;
    asm("{ .reg .u64 t; cvta.to.shared.u64 t, %1; cvt.u32.u64 %0, t; }" : "=r"(a) : "l"(p));
    return a;
}
__device__ __forceinline__ void ldsm_x4(uint32_t* r, uint32_t addr) {
    asm volatile("ldmatrix.sync.aligned.m8n8.x4.shared.b16 {%0,%1,%2,%3}, [%4];"
                 : "=r"(r[0]), "=r"(r[1]), "=r"(r[2]), "=r"(r[3]) : "r"(addr));
}
__device__ __forceinline__ void ldsm_x4_t(uint32_t* r, uint32_t addr) {
    asm volatile("ldmatrix.sync.aligned.m8n8.x4.trans.shared.b16 {%0,%1,%2,%3}, [%4];"
                 : "=r"(r[0]), "=r"(r[1]), "=r"(r[2]), "=r"(r[3]) : "r"(addr));
}
__device__ __forceinline__ void mma_f16(float* d, const uint32_t* a, const uint32_t* b) {
    asm volatile("mma.sync.aligned.m16n8k16.row.col.f32.f16.f16.f32 "
                 "{%0,%1,%2,%3}, {%4,%5,%6,%7}, {%8,%9}, {%0,%1,%2,%3};"
                 : "+f"(d[0]), "+f"(d[1]), "+f"(d[2]), "+f"(d[3])
                 : "r"(a[0]), "r"(a[1]), "r"(a[2]), "r"(a[3]), "r"(b[0]), "r"(b[1]));
}
__device__ __forceinline__ void cp16(uint32_t dst, const void* src, bool pred) {
    asm volatile("cp.async.cg.shared.global [%0], [%1], 16, %2;"
                 :: "r"(dst), "l"(src), "r"(pred ? 16u : 0u));
}
__device__ __forceinline__ void cp_commit() {
    asm volatile("cp.async.commit_group;" ::: "memory");
}

// ================= persistent consumer GEMM: spin on tile flags, overlap with gather =================
#define RSTRIDE_B 272
#define ASTRIDE 144
#define OFF_BH 0
#define OFF_BL (256 * RSTRIDE_B)                        // 69632
#define OFF_A  (2 * 256 * RSTRIDE_B)                    // 139264
#define ABUF(b) (OFF_A + (b) * 128 * ASTRIDE)           // 2 x 18432
#define OFF_C  OFF_A                                    // C tile 128*132*4 = 67584
#define GEMM_SMEM (OFF_A + 67584)                       // 206848

__global__ void __launch_bounds__(256, 1) mma_gemm_kernel(__half* __restrict__ xh_dst,
                                                          float* __restrict__ out, int layer) {
    extern __shared__ char smem[];
    uint32_t sbase = smem_u32(smem);
    int tid = threadIdx.x;
    int wid = tid >> 5, lid = tid & 31;
    int warp_m = wid >> 2, warp_n = wid & 3;      // 2x4 warp grid: 64-row x 32-col warp tiles
    float4 bias4 = ((const float4*)(g_bias + layer * 128))[lid];

    // ---- stage B ONCE (cp.async; resident for all tiles) ----
    {
        const char* gwh = (const char*)g_wfh + (size_t)layer * 65536;
        const char* gwl = (const char*)g_wfl + (size_t)layer * 65536;
        for (int i = tid; i < 8192; i += 256) {
            int m = i >> 12, rem = i & 4095, r = rem >> 4, q = rem & 15;
            uint32_t dst = sbase + (m ? OFF_BL : OFF_BH) + r * RSTRIDE_B + q * 16;
            const char* src = (m ? gwl : gwh) + r * 256 + q * 16;
            cp16(dst, src, true);
        }
        cp_commit();
    }

    auto stageA = [&](int c, int row0) {
        int buf = c & 1;
        const char* gaf = (const char*)g_af;
#pragma unroll
        for (int it = 0; it < 4; it++) {
            int i = tid + it * 256;
            int r = i >> 3, q = i & 7;
            int gr = row0 + r;
            uint32_t dst = sbase + ABUF(buf) + r * ASTRIDE + q * 16;
            const char* src = gaf + (size_t)gr * 512 + c * 128 + q * 16;
            cp16(dst, src, gr < N_NODES);
        }
        cp_commit();
    };

    // ---- persistent tile loop (producer-consumer vs gather) ----
    for (int tile = blockIdx.x; tile < N_TILES; tile += gridDim.x) {
        int row0 = tile * 128;

        // spin until this tile's gather blocks have all signalled
        if (tid == 0) {
            unsigned target = (unsigned)min(16, GATHER_BLOCKS - tile * 16);
            unsigned v;
            do {
                asm volatile("ld.acquire.gpu.u32 %0, [%1];"
                             : "=r"(v) : "l"(g_tilecnt + tile) : "memory");
                if (v >= target) break;
                __nanosleep(128);
            } while (true);
            g_tilecnt[tile] = 0;    // reset for next layer / next replay
        }
        __syncthreads();            // also covers prev epilogue's Cs reads

        stageA(0, row0);
        stageA(1, row0);

        float acc[4][4][4];
#pragma unroll
        for (int mf = 0; mf < 4; mf++)
#pragma unroll
            for (int nf = 0; nf < 4; nf++)
#pragma unroll
                for (int q = 0; q < 4; q++) acc[mf][nf][q] = 0.f;

#pragma unroll
        for (int c = 0; c < 4; c++) {
            if (c < 3) asm volatile("cp.async.wait_group 1;" ::: "memory");
            else       asm volatile("cp.async.wait_group 0;" ::: "memory");
            __syncthreads();

            int buf = c & 1;
            int kb = c * 64;
#pragma unroll
            for (int k16 = 0; k16 < 4; k16++) {
                int k0 = k16 * 16;
                uint32_t ah[4][4];
                int ar = (lid & 15);
                int ac = (k0 + ((lid >> 4) << 3)) * 2;
#pragma unroll
                for (int mf = 0; mf < 4; mf++) {
                    int r = warp_m * 64 + mf * 16 + ar;
                    ldsm_x4(ah[mf], sbase + ABUF(buf) + r * ASTRIDE + ac);
                }
                uint32_t bh[4][2], bl[4][2];
                int br = kb + k0 + (lid & 15);
#pragma unroll
                for (int np = 0; np < 2; np++) {
                    int nc = (warp_n * 32 + np * 16 + ((lid >> 4) << 3)) * 2;
                    uint32_t t[4];
                    ldsm_x4_t(t, sbase + OFF_BH + br * RSTRIDE_B + nc);
                    bh[np * 2][0] = t[0]; bh[np * 2][1] = t[1];
                    bh[np * 2 + 1][0] = t[2]; bh[np * 2 + 1][1] = t[3];
                    ldsm_x4_t(t, sbase + OFF_BL + br * RSTRIDE_B + nc);
                    bl[np * 2][0] = t[0]; bl[np * 2][1] = t[1];
                    bl[np * 2 + 1][0] = t[2]; bl[np * 2 + 1][1] = t[3];
                }
#pragma unroll
                for (int mf = 0; mf < 4; mf++)
#pragma unroll
                    for (int nf = 0; nf < 4; nf++) {
                        mma_f16(acc[mf][nf], ah[mf], bh[nf]);  // A * Whi
                        mma_f16(acc[mf][nf], ah[mf], bl[nf]);  // A * Wlo
                    }
            }
            __syncthreads();
            if (c + 2 < 4) stageA(c + 2, row0);
        }

        // ---- dump accumulators to SMEM C tile (aliases A region) ----
        float* Cs = (float*)(smem + OFF_C);
#pragma unroll
        for (int mf = 0; mf < 4; mf++)
#pragma unroll
            for (int nf = 0; nf < 4; nf++) {
                int r = warp_m * 64 + mf * 16 + (lid >> 2);
                int cc = warp_n * 32 + nf * 8 + (lid & 3) * 2;
                *(float2*)&Cs[r * 132 + cc]       = make_float2(acc[mf][nf][0], acc[mf][nf][1]);
                *(float2*)&Cs[(r + 8) * 132 + cc] = make_float2(acc[mf][nf][2], acc[mf][nf][3]);
            }
        __syncthreads();

        // ---- epilogue: warp per row — bias + leaky + L2 norm + stores (xh_dst + out) ----
#pragma unroll
        for (int it = 0; it < 16; it++) {
            int row = it * 8 + wid;
            int gr = row0 + row;
            float4 v = *(float4*)&Cs[row * 132 + lid * 4];
            float t0 = v.x + bias4.x, t1 = v.y + bias4.y;
            float t2 = v.z + bias4.z, t3 = v.w + bias4.w;
            t0 = (t0 > 0.f) ? t0 : 0.01f * t0;
            t1 = (t1 > 0.f) ? t1 : 0.01f * t1;
            t2 = (t2 > 0.f) ? t2 : 0.01f * t2;
            t3 = (t3 > 0.f) ? t3 : 0.01f * t3;
            float ss = fmaf(t0, t0, fmaf(t1, t1, fmaf(t2, t2, t3 * t3)));
            ss += __shfl_xor_sync(0xffffffffu, ss, 16);
            ss += __shfl_xor_sync(0xffffffffu, ss, 8);
            ss += __shfl_xor_sync(0xffffffffu, ss, 4);
            ss += __shfl_xor_sync(0xffffffffu, ss, 2);
            ss += __shfl_xor_sync(0xffffffffu, ss, 1);
            float sc = 1.0f / fmaxf(sqrtf(ss), 1e-12f);
            if (gr < N_NODES) {
                float4 o = make_float4(t0 * sc, t1 * sc, t2 * sc, t3 * sc);
                ((float4*)&out[(size_t)gr * 384 + (size_t)(layer + 1) * 128])[lid] = o;
                __half2 h0 = __floats2half2_rn(o.x, o.y);
                __half2 h1 = __floats2half2_rn(o.z, o.w);
                ((uint2*)xh_dst)[(size_t)gr * 32 + lid] = make_uint2(*(uint32_t*)&h0, *(uint32_t*)&h1);
            }
        }
    }
}

// ================= launch: fork gemm onto a second captured stream =================
extern "C" void kernel_launch(void* const* d_in, const int* in_sizes, int n_in,
                              void* d_out, int out_size) {
    const int*   adj_row  = (const int*)d_in[0];
    const int*   adj_col  = (const int*)d_in[1];
    const float* adj_vals = (const float*)d_in[2];
    const float* emb      = (const float*)d_in[3];
    const float* W1w      = (const float*)d_in[4];
    const float* W1b      = (const float*)d_in[5];
    const float* W2w      = (const float*)d_in[6];
    const float* W2b      = (const float*)d_in[7];
    float* out = (float*)d_out;

    cudaFuncSetAttribute(mma_gemm_kernel, cudaFuncAttributeMaxDynamicSharedMemorySize, GEMM_SMEM);

    __half* xa;
    __half* xb;
    cudaGetSymbolAddress((void**)&xa, g_xha);
    cudaGetSymbolAddress((void**)&xb, g_xhb);

    cudaStream_t s2;
    cudaStreamCreateWithFlags(&s2, cudaStreamNonBlocking);
    cudaEvent_t ev0, ev1, ev2;
    cudaEventCreateWithFlags(&ev0, cudaEventDisableTiming);
    cudaEventCreateWithFlags(&ev1, cudaEventDisableTiming);
    cudaEventCreateWithFlags(&ev2, cudaEventDisableTiming);

    setup_kernel<<<(SETUP_N + 255) / 256, 256>>>(emb, out, W1w, W1b, W2w, W2b, adj_row);
    bsum_kernel<<<NBLK, 256>>>();
    pscan_kernel<<<NBLK, 256>>>();
    scatter_kernel<<<(NNZ + 255) / 256, 256>>>(adj_row, adj_col, adj_vals);

    cudaEventRecord(ev0, 0);
    cudaStreamWaitEvent(s2, ev0, 0);

    // layer 0: gather (stream 0) || gemm (s2) coupled via tile flags
    gather_kernel<<<GATHER_BLOCKS, 256>>>(xa);
    mma_gemm_kernel<<<GEMM_GRID, 256, GEMM_SMEM, s2>>>(xb, out, 0);
    cudaEventRecord(ev1, s2);
    cudaStreamWaitEvent((cudaStream_t)0, ev1, 0);   // gather1 needs gemm0's xh output

    // layer 1
    gather_kernel<<<GATHER_BLOCKS, 256>>>(xb);
    mma_gemm_kernel<<<GEMM_GRID, 256, GEMM_SMEM, s2>>>(xa, out, 1);
    cudaEventRecord(ev2, s2);
    cudaStreamWaitEvent((cudaStream_t)0, ev2, 0);   // join back to capture stream
}